// round 3
// baseline (speedup 1.0000x reference)
#include <cuda_runtime.h>
#include <cstdint>

#define NUM_NODES 10000
#define NUM_EDGES 640000
#define F 128

// Scratch (device globals — no allocation allowed)
__device__ float g_agg[(size_t)NUM_NODES * F];
__device__ float g_deg[NUM_NODES];

// ---------------------------------------------------------------------------
// Kernel 1: zero the scratch buffers
// ---------------------------------------------------------------------------
__global__ void zero_kernel() {
    const int total = NUM_NODES * F + NUM_NODES;
    for (int i = blockIdx.x * blockDim.x + threadIdx.x; i < total;
         i += gridDim.x * blockDim.x) {
        if (i < NUM_NODES * F) g_agg[i] = 0.0f;
        else                   g_deg[i - NUM_NODES * F] = 0.0f;
    }
}

// ---------------------------------------------------------------------------
// Kernel 2: scatter-add. One warp per edge; each lane handles 4 features
// (float4 gather from x[src], 4 scalar atomicAdds into g_agg[dst]).
// Lane 0 additionally bumps the degree counter.
// edge_index arrives as int32 (JAX default coerces int64 -> int32).
// ---------------------------------------------------------------------------
__global__ void scatter_kernel(const float* __restrict__ x,
                               const int* __restrict__ ei) {
    int gtid = blockIdx.x * blockDim.x + threadIdx.x;
    int edge = gtid >> 5;
    int lane = gtid & 31;
    if (edge >= NUM_EDGES) return;

    int src = ei[edge];
    int dst = ei[NUM_EDGES + edge];
    // Guard: if dtype assumption is wrong we get a visible rel_err, not a crash.
    if ((unsigned)src >= NUM_NODES || (unsigned)dst >= NUM_NODES) return;

    const float4* xs = reinterpret_cast<const float4*>(x + (size_t)src * F);
    float4 v = __ldg(&xs[lane]);

    float* ag = g_agg + (size_t)dst * F + lane * 4;
    atomicAdd(ag + 0, v.x);
    atomicAdd(ag + 1, v.y);
    atomicAdd(ag + 2, v.z);
    atomicAdd(ag + 3, v.w);

    if (lane == 0) atomicAdd(&g_deg[dst], 1.0f);
}

// ---------------------------------------------------------------------------
// Kernel 3: h = agg/max(deg,1) + x ; out = relu(h @ W^T + b)
// 128 threads/block; thread t owns output feature t.
// Weight row W[t][:] (== the column of W^T this thread needs) is contiguous
// in global memory -> loaded into REGISTERS once per block (32 x float4).
// Only a 2KB static shared buffer for the staged h vectors.
// ---------------------------------------------------------------------------
#define NODES_PER_ITER 4

__global__ void __launch_bounds__(F)
gemm_kernel(const float* __restrict__ x,
            const float* __restrict__ W,
            const float* __restrict__ b,
            float* __restrict__ out) {
    __shared__ float hs[NODES_PER_ITER * F];

    const int t = threadIdx.x;  // 0..127 (output feature)

    // Load this thread's weight row into registers (one-time, L2-resident W)
    float wreg[F];
    const float4* wrow = reinterpret_cast<const float4*>(W + (size_t)t * F);
    #pragma unroll
    for (int i = 0; i < F / 4; i++) {
        float4 v = __ldg(&wrow[i]);
        wreg[4 * i + 0] = v.x;
        wreg[4 * i + 1] = v.y;
        wreg[4 * i + 2] = v.z;
        wreg[4 * i + 3] = v.w;
    }
    const float bv = __ldg(&b[t]);

    const int nodesPerBlock = (NUM_NODES + gridDim.x - 1) / gridDim.x;
    const int n0 = blockIdx.x * nodesPerBlock;
    const int n1 = min(n0 + nodesPerBlock, NUM_NODES);

    for (int n = n0; n < n1; n += NODES_PER_ITER) {
        const int cnt = min(NODES_PER_ITER, n1 - n);
        __syncthreads();  // protect hs reuse across iterations
        for (int k = 0; k < cnt; k++) {
            const int node = n + k;
            const float deg = fmaxf(g_deg[node], 1.0f);
            hs[k * F + t] = g_agg[(size_t)node * F + t] / deg
                          + x[(size_t)node * F + t];
        }
        __syncthreads();

        float a0 = bv, a1 = bv, a2 = bv, a3 = bv;
        #pragma unroll
        for (int d = 0; d < F; d++) {
            const float w = wreg[d];
            a0 = fmaf(hs[d],         w, a0);   // LDS broadcasts
            a1 = fmaf(hs[F + d],     w, a1);
            a2 = fmaf(hs[2 * F + d], w, a2);
            a3 = fmaf(hs[3 * F + d], w, a3);
        }
        /* */        out[(size_t)(n    ) * F + t] = fmaxf(a0, 0.0f);
        if (cnt > 1) out[(size_t)(n + 1) * F + t] = fmaxf(a1, 0.0f);
        if (cnt > 2) out[(size_t)(n + 2) * F + t] = fmaxf(a2, 0.0f);
        if (cnt > 3) out[(size_t)(n + 3) * F + t] = fmaxf(a3, 0.0f);
    }
}

// ---------------------------------------------------------------------------
extern "C" void kernel_launch(void* const* d_in, const int* in_sizes, int n_in,
                              void* d_out, int out_size) {
    const float* x  = (const float*)d_in[0];
    const int*   ei = (const int*)d_in[1];
    const float* W  = (const float*)d_in[2];
    const float* b  = (const float*)d_in[3];
    float*       out = (float*)d_out;

    // 1) zero scratch
    zero_kernel<<<1280, 256>>>();

    // 2) scatter-add (warp per edge)
    const long long total_threads = (long long)NUM_EDGES * 32;
    const int sblocks = (int)((total_threads + 255) / 256);
    scatter_kernel<<<sblocks, 256>>>(x, ei);

    // 3) normalize + GEMM + bias + relu
    gemm_kernel<<<296, F>>>(x, W, b, out);
}

// round 4
// speedup vs baseline: 1.3173x; 1.3173x over previous
#include <cuda_runtime.h>
#include <cstdint>

#define NUM_NODES 10000
#define NUM_EDGES 640000
#define F 128

// Scratch (device globals — no allocation allowed)
__device__ float g_agg[(size_t)NUM_NODES * F];
__device__ float g_deg[NUM_NODES];

// ---------------------------------------------------------------------------
// Kernel 1: zero the scratch buffers (float4 stores)
// ---------------------------------------------------------------------------
__global__ void zero_kernel() {
    const int total4 = (NUM_NODES * F) / 4;  // g_agg as float4
    float4 z = make_float4(0.f, 0.f, 0.f, 0.f);
    float4* a4 = reinterpret_cast<float4*>(g_agg);
    int i = blockIdx.x * blockDim.x + threadIdx.x;
    for (; i < total4; i += gridDim.x * blockDim.x) a4[i] = z;
    int j = blockIdx.x * blockDim.x + threadIdx.x;
    if (j < NUM_NODES) g_deg[j] = 0.0f;
}

// ---------------------------------------------------------------------------
// Kernel 2: scatter-add. One warp per edge; each lane handles 4 features:
// one float4 gather from x[src], ONE red.global.add.v4.f32 into g_agg[dst]
// (4x fewer LTS atomic transactions than scalar atomicAdd).
// Lane 0 additionally bumps the degree counter.
// ---------------------------------------------------------------------------
__global__ void scatter_kernel(const float* __restrict__ x,
                               const int* __restrict__ ei) {
    int gtid = blockIdx.x * blockDim.x + threadIdx.x;
    int edge = gtid >> 5;
    int lane = gtid & 31;
    if (edge >= NUM_EDGES) return;

    int src = ei[edge];
    int dst = ei[NUM_EDGES + edge];
    if ((unsigned)src >= NUM_NODES || (unsigned)dst >= NUM_NODES) return;

    const float4* xs = reinterpret_cast<const float4*>(x + (size_t)src * F);
    float4 v = __ldg(&xs[lane]);

    float* ag = g_agg + (size_t)dst * F + lane * 4;
    asm volatile("red.global.add.v4.f32 [%0], {%1, %2, %3, %4};"
                 :: "l"(ag), "f"(v.x), "f"(v.y), "f"(v.z), "f"(v.w)
                 : "memory");

    if (lane == 0) atomicAdd(&g_deg[dst], 1.0f);
}

// ---------------------------------------------------------------------------
// Kernel 3: h = agg/max(deg,1) + x ; out = relu(h @ W^T + b)
// 128 threads/block; thread t owns output feature t; weight row in registers.
// ---------------------------------------------------------------------------
#define NODES_PER_ITER 4

__global__ void __launch_bounds__(F)
gemm_kernel(const float* __restrict__ x,
            const float* __restrict__ W,
            const float* __restrict__ b,
            float* __restrict__ out) {
    __shared__ float hs[NODES_PER_ITER * F];

    const int t = threadIdx.x;  // 0..127 (output feature)

    float wreg[F];
    const float4* wrow = reinterpret_cast<const float4*>(W + (size_t)t * F);
    #pragma unroll
    for (int i = 0; i < F / 4; i++) {
        float4 v = __ldg(&wrow[i]);
        wreg[4 * i + 0] = v.x;
        wreg[4 * i + 1] = v.y;
        wreg[4 * i + 2] = v.z;
        wreg[4 * i + 3] = v.w;
    }
    const float bv = __ldg(&b[t]);

    const int nodesPerBlock = (NUM_NODES + gridDim.x - 1) / gridDim.x;
    const int n0 = blockIdx.x * nodesPerBlock;
    const int n1 = min(n0 + nodesPerBlock, NUM_NODES);

    for (int n = n0; n < n1; n += NODES_PER_ITER) {
        const int cnt = min(NODES_PER_ITER, n1 - n);
        __syncthreads();
        for (int k = 0; k < cnt; k++) {
            const int node = n + k;
            const float deg = fmaxf(g_deg[node], 1.0f);
            hs[k * F + t] = g_agg[(size_t)node * F + t] / deg
                          + x[(size_t)node * F + t];
        }
        __syncthreads();

        float a0 = bv, a1 = bv, a2 = bv, a3 = bv;
        #pragma unroll
        for (int d = 0; d < F; d++) {
            const float w = wreg[d];
            a0 = fmaf(hs[d],         w, a0);
            a1 = fmaf(hs[F + d],     w, a1);
            a2 = fmaf(hs[2 * F + d], w, a2);
            a3 = fmaf(hs[3 * F + d], w, a3);
        }
        /* */        out[(size_t)(n    ) * F + t] = fmaxf(a0, 0.0f);
        if (cnt > 1) out[(size_t)(n + 1) * F + t] = fmaxf(a1, 0.0f);
        if (cnt > 2) out[(size_t)(n + 2) * F + t] = fmaxf(a2, 0.0f);
        if (cnt > 3) out[(size_t)(n + 3) * F + t] = fmaxf(a3, 0.0f);
    }
}

// ---------------------------------------------------------------------------
extern "C" void kernel_launch(void* const* d_in, const int* in_sizes, int n_in,
                              void* d_out, int out_size) {
    const float* x  = (const float*)d_in[0];
    const int*   ei = (const int*)d_in[1];
    const float* W  = (const float*)d_in[2];
    const float* b  = (const float*)d_in[3];
    float*       out = (float*)d_out;

    // 1) zero scratch
    zero_kernel<<<1280, 256>>>();

    // 2) scatter-add (warp per edge, vector RED)
    const long long total_threads = (long long)NUM_EDGES * 32;
    const int sblocks = (int)((total_threads + 255) / 256);
    scatter_kernel<<<sblocks, 256>>>(x, ei);

    // 3) normalize + GEMM + bias + relu
    gemm_kernel<<<296, F>>>(x, W, b, out);
}

// round 5
// speedup vs baseline: 2.3884x; 1.8131x over previous
#include <cuda_runtime.h>
#include <cstdint>

#define NUM_NODES 10000
#define NUM_EDGES 640000
#define F 128

// Scratch (device globals — no allocation allowed)
__device__ int   g_cnt[NUM_NODES];
__device__ int   g_off[NUM_NODES + 1];
__device__ int   g_cursor[NUM_NODES];
__device__ int   g_bucket[NUM_EDGES];
__device__ float g_h[(size_t)NUM_NODES * F];   // h = agg/deg + x

// ---------------------------------------------------------------------------
// 1) zero histogram counters
// ---------------------------------------------------------------------------
__global__ void zero_cnt_kernel() {
    int i = blockIdx.x * blockDim.x + threadIdx.x;
    if (i < NUM_NODES) g_cnt[i] = 0;
}

// ---------------------------------------------------------------------------
// 2) histogram of dst (int atomics only)
// ---------------------------------------------------------------------------
__global__ void hist_kernel(const int* __restrict__ ei) {
    int e = blockIdx.x * blockDim.x + threadIdx.x;
    if (e >= NUM_EDGES) return;
    int dst = ei[NUM_EDGES + e];
    if ((unsigned)dst < NUM_NODES) atomicAdd(&g_cnt[dst], 1);
}

// ---------------------------------------------------------------------------
// 3) exclusive scan of counts (single block, 256 threads x 40 elems)
//    writes g_off[0..N] and initializes g_cursor = g_off[0..N-1]
// ---------------------------------------------------------------------------
#define SCAN_T 256
#define SCAN_PER 40   // 256*40 = 10240 >= 10000

__global__ void scan_kernel() {
    __shared__ int part[SCAN_T];
    const int t = threadIdx.x;
    const int base = t * SCAN_PER;

    int local[SCAN_PER];
    int s = 0;
    #pragma unroll
    for (int k = 0; k < SCAN_PER; k++) {
        int i = base + k;
        int c = (i < NUM_NODES) ? g_cnt[i] : 0;
        local[k] = s;          // exclusive within chunk
        s += c;
    }
    part[t] = s;
    __syncthreads();

    // inclusive scan over 256 partials (Hillis-Steele)
    #pragma unroll
    for (int d = 1; d < SCAN_T; d <<= 1) {
        int v = (t >= d) ? part[t - d] : 0;
        __syncthreads();
        part[t] += v;
        __syncthreads();
    }
    const int tbase = part[t] - s;   // exclusive base for this thread

    #pragma unroll
    for (int k = 0; k < SCAN_PER; k++) {
        int i = base + k;
        if (i < NUM_NODES) {
            int o = tbase + local[k];
            g_off[i] = o;
            g_cursor[i] = o;
        }
    }
    if (t == SCAN_T - 1) g_off[NUM_NODES] = part[SCAN_T - 1];
}

// ---------------------------------------------------------------------------
// 4) fill buckets: bucket[cursor[dst]++] = src
// ---------------------------------------------------------------------------
__global__ void fill_kernel(const int* __restrict__ ei) {
    int e = blockIdx.x * blockDim.x + threadIdx.x;
    if (e >= NUM_EDGES) return;
    int src = ei[e];
    int dst = ei[NUM_EDGES + e];
    if ((unsigned)src >= NUM_NODES || (unsigned)dst >= NUM_NODES) return;
    int pos = atomicAdd(&g_cursor[dst], 1);
    g_bucket[pos] = src;
}

// ---------------------------------------------------------------------------
// 5) segmented reduce: warp per node. Lane owns 4 features (float4).
//    4-edge unroll -> 4 independent float4 accumulators (MLP=4).
//    h = sum / max(deg,1) + x[node]. No float atomics anywhere.
// ---------------------------------------------------------------------------
__global__ void __launch_bounds__(256)
reduce_kernel(const float* __restrict__ x) {
    int gtid = blockIdx.x * blockDim.x + threadIdx.x;
    int node = gtid >> 5;
    int lane = gtid & 31;
    if (node >= NUM_NODES) return;

    const int start = g_off[node];
    const int end   = g_off[node + 1];
    const float inv_deg = 1.0f / fmaxf((float)(end - start), 1.0f);

    float4 a0 = make_float4(0.f, 0.f, 0.f, 0.f);
    float4 a1 = a0, a2 = a0, a3 = a0;

    int e = start;
    for (; e + 4 <= end; e += 4) {
        int s0 = g_bucket[e + 0];
        int s1 = g_bucket[e + 1];
        int s2 = g_bucket[e + 2];
        int s3 = g_bucket[e + 3];
        float4 v0 = __ldg(reinterpret_cast<const float4*>(x + (size_t)s0 * F) + lane);
        float4 v1 = __ldg(reinterpret_cast<const float4*>(x + (size_t)s1 * F) + lane);
        float4 v2 = __ldg(reinterpret_cast<const float4*>(x + (size_t)s2 * F) + lane);
        float4 v3 = __ldg(reinterpret_cast<const float4*>(x + (size_t)s3 * F) + lane);
        a0.x += v0.x; a0.y += v0.y; a0.z += v0.z; a0.w += v0.w;
        a1.x += v1.x; a1.y += v1.y; a1.z += v1.z; a1.w += v1.w;
        a2.x += v2.x; a2.y += v2.y; a2.z += v2.z; a2.w += v2.w;
        a3.x += v3.x; a3.y += v3.y; a3.z += v3.z; a3.w += v3.w;
    }
    for (; e < end; e++) {
        int s = g_bucket[e];
        float4 v = __ldg(reinterpret_cast<const float4*>(x + (size_t)s * F) + lane);
        a0.x += v.x; a0.y += v.y; a0.z += v.z; a0.w += v.w;
    }

    float4 sum;
    sum.x = (a0.x + a1.x) + (a2.x + a3.x);
    sum.y = (a0.y + a1.y) + (a2.y + a3.y);
    sum.z = (a0.z + a1.z) + (a2.z + a3.z);
    sum.w = (a0.w + a1.w) + (a2.w + a3.w);

    float4 xd = __ldg(reinterpret_cast<const float4*>(x + (size_t)node * F) + lane);
    float4 h;
    h.x = sum.x * inv_deg + xd.x;
    h.y = sum.y * inv_deg + xd.y;
    h.z = sum.z * inv_deg + xd.z;
    h.w = sum.w * inv_deg + xd.w;

    reinterpret_cast<float4*>(g_h + (size_t)node * F)[lane] = h;
}

// ---------------------------------------------------------------------------
// 6) out = relu(h @ W^T + b). 128 threads/block; thread t owns feature t;
//    weight row W[t][:] in registers; 4 nodes staged in shared per pass.
// ---------------------------------------------------------------------------
#define NODES_PER_ITER 4

__global__ void __launch_bounds__(F)
gemm_kernel(const float* __restrict__ W,
            const float* __restrict__ b,
            float* __restrict__ out) {
    __shared__ float hs[NODES_PER_ITER * F];

    const int t = threadIdx.x;

    float wreg[F];
    const float4* wrow = reinterpret_cast<const float4*>(W + (size_t)t * F);
    #pragma unroll
    for (int i = 0; i < F / 4; i++) {
        float4 v = __ldg(&wrow[i]);
        wreg[4 * i + 0] = v.x;
        wreg[4 * i + 1] = v.y;
        wreg[4 * i + 2] = v.z;
        wreg[4 * i + 3] = v.w;
    }
    const float bv = __ldg(&b[t]);

    const int nodesPerBlock = (NUM_NODES + gridDim.x - 1) / gridDim.x;
    const int n0 = blockIdx.x * nodesPerBlock;
    const int n1 = min(n0 + nodesPerBlock, NUM_NODES);

    for (int n = n0; n < n1; n += NODES_PER_ITER) {
        const int cnt = min(NODES_PER_ITER, n1 - n);
        __syncthreads();
        for (int k = 0; k < cnt; k++)
            hs[k * F + t] = g_h[(size_t)(n + k) * F + t];
        __syncthreads();

        float a0 = bv, a1 = bv, a2 = bv, a3 = bv;
        #pragma unroll
        for (int d = 0; d < F; d++) {
            const float w = wreg[d];
            a0 = fmaf(hs[d],         w, a0);
            a1 = fmaf(hs[F + d],     w, a1);
            a2 = fmaf(hs[2 * F + d], w, a2);
            a3 = fmaf(hs[3 * F + d], w, a3);
        }
        /* */        out[(size_t)(n    ) * F + t] = fmaxf(a0, 0.0f);
        if (cnt > 1) out[(size_t)(n + 1) * F + t] = fmaxf(a1, 0.0f);
        if (cnt > 2) out[(size_t)(n + 2) * F + t] = fmaxf(a2, 0.0f);
        if (cnt > 3) out[(size_t)(n + 3) * F + t] = fmaxf(a3, 0.0f);
    }
}

// ---------------------------------------------------------------------------
extern "C" void kernel_launch(void* const* d_in, const int* in_sizes, int n_in,
                              void* d_out, int out_size) {
    const float* x  = (const float*)d_in[0];
    const int*   ei = (const int*)d_in[1];
    const float* W  = (const float*)d_in[2];
    const float* b  = (const float*)d_in[3];
    float*       out = (float*)d_out;

    const int eblocks = (NUM_EDGES + 255) / 256;

    zero_cnt_kernel<<<(NUM_NODES + 255) / 256, 256>>>();
    hist_kernel<<<eblocks, 256>>>(ei);
    scan_kernel<<<1, SCAN_T>>>();
    fill_kernel<<<eblocks, 256>>>(ei);

    const int rblocks = (NUM_NODES * 32 + 255) / 256;
    reduce_kernel<<<rblocks, 256>>>(x);

    gemm_kernel<<<296, F>>>(W, b, out);
}